// round 6
// baseline (speedup 1.0000x reference)
#include <cuda_runtime.h>
#include <cuda_bf16.h>
#include <cstdint>

// LNLieBracketChannelMix via mma.sync bf16-split.
// R6 = R5 with alignment fix: global bf16 scratch arrays are __align__(256)
// so 16B cp.async / uint2 accesses are legal (R5 container crash suspect).

#define B_    8
#define F_    256
#define NDIM  4096
#define COLS  12288
#define GT    64
#define NT    32
#define CT    96
#define KC    32
#define NCH   8
#define THREADS 256

#define A_STRIDE 80
#define B_STRIDE 208
#define A_PART   (GT * A_STRIDE)        // 5120
#define B_PART   (KC * B_STRIDE)        // 6656
#define BH_OFF   (4 * A_PART)           // 20480
#define STAGE    (BH_OFF + 2 * B_PART)  // 33792
#define SMEM_TOTAL (2 * STAGE)          // 67584

// global bf16 scratch (static allocation allowed); 256B-aligned for cp.async
__device__ __align__(256) __nv_bfloat16 g_xh[(size_t)B_ * F_ * COLS];
__device__ __align__(256) __nv_bfloat16 g_xl[(size_t)B_ * F_ * COLS];
__device__ __align__(256) __nv_bfloat16 g_wsplit[4][F_ * F_];   // w1h,w1l,w2h,w2l

static __device__ __forceinline__ uint32_t s2u(const void* p) {
    uint32_t a;
    asm("{ .reg .u64 t; cvta.to.shared.u64 t, %1; cvt.u32.u64 %0, t; }" : "=r"(a) : "l"(p));
    return a;
}
static __device__ __forceinline__ void cp16(uint32_t dst, const void* src) {
    asm volatile("cp.async.cg.shared.global [%0], [%1], 16;" :: "r"(dst), "l"(src));
}
#define CP_COMMIT() asm volatile("cp.async.commit_group;" ::: "memory")
#define CP_WAIT(n)  asm volatile("cp.async.wait_group %0;" :: "n"(n) : "memory")

static __device__ __forceinline__ void lm4(uint32_t* r, uint32_t a) {
    asm volatile("ldmatrix.sync.aligned.m8n8.x4.shared.b16 {%0,%1,%2,%3}, [%4];"
        : "=r"(r[0]), "=r"(r[1]), "=r"(r[2]), "=r"(r[3]) : "r"(a));
}
static __device__ __forceinline__ void lm4t(uint32_t* r, uint32_t a) {
    asm volatile("ldmatrix.sync.aligned.m8n8.x4.trans.shared.b16 {%0,%1,%2,%3}, [%4];"
        : "=r"(r[0]), "=r"(r[1]), "=r"(r[2]), "=r"(r[3]) : "r"(a));
}
static __device__ __forceinline__ void mma(float* d, const uint32_t* a, uint32_t b0, uint32_t b1) {
    asm volatile(
        "mma.sync.aligned.m16n8k16.row.col.f32.bf16.bf16.f32 "
        "{%0,%1,%2,%3}, {%4,%5,%6,%7}, {%8,%9}, {%0,%1,%2,%3};"
        : "+f"(d[0]), "+f"(d[1]), "+f"(d[2]), "+f"(d[3])
        : "r"(a[0]), "r"(a[1]), "r"(a[2]), "r"(a[3]), "r"(b0), "r"(b1));
}
static __device__ __forceinline__ uint32_t pk2(__nv_bfloat16 a, __nv_bfloat16 b) {
    __nv_bfloat162 t = __halves2bfloat162(a, b);
    return *reinterpret_cast<uint32_t*>(&t);
}
static __device__ __forceinline__ void split4(float4 w, uint2& hv, uint2& lv) {
    __nv_bfloat16 hx = __float2bfloat16(w.x), hy = __float2bfloat16(w.y);
    __nv_bfloat16 hz = __float2bfloat16(w.z), hw = __float2bfloat16(w.w);
    hv.x = pk2(hx, hy); hv.y = pk2(hz, hw);
    lv.x = pk2(__float2bfloat16(w.x - __bfloat162float(hx)),
               __float2bfloat16(w.y - __bfloat162float(hy)));
    lv.y = pk2(__float2bfloat16(w.z - __bfloat162float(hz)),
               __float2bfloat16(w.w - __bfloat162float(hw)));
}

__global__ __launch_bounds__(256) void cvt_x_kernel(const float* __restrict__ x) {
    size_t total = (size_t)B_ * F_ * COLS / 4;
    for (size_t i = (size_t)blockIdx.x * blockDim.x + threadIdx.x;
         i < total; i += (size_t)gridDim.x * blockDim.x) {
        float4 v = ((const float4*)x)[i];
        uint2 hv, lv; split4(v, hv, lv);
        ((uint2*)g_xh)[i] = hv;
        ((uint2*)g_xl)[i] = lv;
    }
}
__global__ __launch_bounds__(256) void cvt_w_kernel(const float* __restrict__ W1,
                                                    const float* __restrict__ W2) {
    int i = blockIdx.x * blockDim.x + threadIdx.x;
    if (i < F_ * F_ / 4) {
        float4 v1 = ((const float4*)W1)[i];
        uint2 hv, lv; split4(v1, hv, lv);
        ((uint2*)g_wsplit[0])[i] = hv;
        ((uint2*)g_wsplit[1])[i] = lv;
        float4 v2 = ((const float4*)W2)[i];
        split4(v2, hv, lv);
        ((uint2*)g_wsplit[2])[i] = hv;
        ((uint2*)g_wsplit[3])[i] = lv;
    }
}

__global__ __launch_bounds__(THREADS, 2)
void lnlb_mma_kernel(const float* __restrict__ x,
                     const float* __restrict__ M1,
                     const float* __restrict__ M2,
                     float* __restrict__ out)
{
    extern __shared__ char smem[];
    const uint32_t sb = s2u(smem);

    const int tid = threadIdx.x;
    const int warp = tid >> 5, lane = tid & 31;
    const int n0 = blockIdx.x * NT;
    const int g0 = blockIdx.y * GT;
    const int b  = blockIdx.z;
    const size_t xoff = (size_t)b * F_ * COLS;

    const int mat = warp >> 2;           // 0 -> D1, 1 -> D2
    const int q   = warp & 3;
    const int wg  = (q >> 1) * 32;
    const int wc  = (q & 1) * 48;

    float acc[2][6][4];
    #pragma unroll
    for (int m = 0; m < 2; m++)
        #pragma unroll
        for (int t = 0; t < 6; t++)
            #pragma unroll
            for (int j = 0; j < 4; j++) acc[m][t][j] = 0.f;

    const int lrow = lane & 15;
    const uint32_t lhA = (lane & 16) ? 16u : 0u;
    const uint32_t lhB = (lane & 16) ? 8u  : 0u;
    uint32_t aoff[2], boff[3];
    #pragma unroll
    for (int m = 0; m < 2; m++) aoff[m] = (uint32_t)((wg + 16 * m + lrow) * A_STRIDE) + lhA;
    #pragma unroll
    for (int t = 0; t < 3; t++) boff[t] = (uint32_t)(lrow * B_STRIDE + (wc + t * 16 + lhB) * 2);

    const uint32_t aBaseH = (uint32_t)(mat * 2 * A_PART);
    const uint32_t aBaseL = aBaseH + (uint32_t)A_PART;

    // staging: pure cp.async of pre-split bf16 (16B chunks)
    auto stage = [&](int c, uint32_t bufu) {
        const int f0 = c * KC;
        // A: 4 tiles x 64 rows x 4 chunks of 16B
        #pragma unroll
        for (int i = tid; i < 1024; i += THREADS) {
            int t = i >> 8, r = i & 255, g = r >> 2, fq = r & 3;
            cp16(bufu + (uint32_t)(t * A_PART + g * A_STRIDE + fq * 16),
                 &g_wsplit[t][(g0 + g) * F_ + f0 + fq * 8]);
        }
        // B: 2 tiles x 32 rows x 12 chunks of 16B
        #pragma unroll
        for (int i = tid; i < 768; i += THREADS) {
            int t = i / 384, r = i % 384, f = r / 12, cq = r % 12;
            const __nv_bfloat16* src = (t ? g_xl : g_xh) + xoff
                + (size_t)(f0 + f) * COLS + (cq >> 2) * NDIM + n0 + (cq & 3) * 8;
            cp16(bufu + (uint32_t)(BH_OFF + t * B_PART + f * B_STRIDE + cq * 16), src);
        }
    };

    stage(0, sb);
    CP_COMMIT();

    for (int c = 0; c < NCH; ++c) {
        if (c + 1 < NCH) { stage(c + 1, sb + (uint32_t)(((c + 1) & 1) * STAGE)); CP_COMMIT(); CP_WAIT(1); }
        else CP_WAIT(0);
        __syncthreads();

        const uint32_t bu = sb + (uint32_t)((c & 1) * STAGE);
        #pragma unroll
        for (int ks2 = 0; ks2 < 2; ++ks2) {
            const uint32_t ksA = ks2 * 32;
            const uint32_t ksB = ks2 * 16 * B_STRIDE;

            uint32_t Ah[2][4], Al[2][4];
            #pragma unroll
            for (int m = 0; m < 2; m++) {
                lm4(Ah[m], bu + aBaseH + aoff[m] + ksA);
                lm4(Al[m], bu + aBaseL + aoff[m] + ksA);
            }
            uint32_t BH[3][4], BL[3][4];
            #pragma unroll
            for (int t = 0; t < 3; t++) {
                lm4t(BH[t], bu + BH_OFF + boff[t] + ksB);
                lm4t(BL[t], bu + BH_OFF + B_PART + boff[t] + ksB);
            }
            #pragma unroll
            for (int m = 0; m < 2; m++)
                #pragma unroll
                for (int t = 0; t < 3; t++) {
                    mma(acc[m][2*t],   Ah[m], BH[t][0], BH[t][1]);
                    mma(acc[m][2*t+1], Ah[m], BH[t][2], BH[t][3]);
                }
            #pragma unroll
            for (int m = 0; m < 2; m++)
                #pragma unroll
                for (int t = 0; t < 3; t++) {
                    mma(acc[m][2*t],   Ah[m], BL[t][0], BL[t][1]);
                    mma(acc[m][2*t+1], Ah[m], BL[t][2], BL[t][3]);
                }
            #pragma unroll
            for (int m = 0; m < 2; m++)
                #pragma unroll
                for (int t = 0; t < 3; t++) {
                    mma(acc[m][2*t],   Al[m], BH[t][0], BH[t][1]);
                    mma(acc[m][2*t+1], Al[m], BH[t][2], BH[t][3]);
                }
        }
        __syncthreads();
    }

    // dump accumulators to smem (reuse stage buffers)
    float* D1s = (float*)smem;
    float* D2s = D1s + GT * CT;
    {
        float* Ds = mat ? D2s : D1s;
        const int dr = wg + (lane >> 2);
        const int dc = wc + (lane & 3) * 2;
        #pragma unroll
        for (int m = 0; m < 2; m++)
            #pragma unroll
            for (int t = 0; t < 6; t++) {
                int r0 = dr + 16 * m, cc = dc + t * 8;
                Ds[r0 * CT + cc]         = acc[m][t][0];
                Ds[r0 * CT + cc + 1]     = acc[m][t][1];
                Ds[(r0 + 8) * CT + cc]   = acc[m][t][2];
                Ds[(r0 + 8) * CT + cc+1] = acc[m][t][3];
            }
    }
    __syncthreads();

    // epilogue
    float m1[9], m2[9];
    #pragma unroll
    for (int i = 0; i < 9; i++) { m1[i] = M1[i]; m2[i] = M2[i]; }

    #pragma unroll
    for (int p = tid; p < GT * NT; p += THREADS) {
        int g = p >> 5, nn = p & 31;
        float e10 = D1s[g * CT + 0 * NT + nn];
        float e11 = D1s[g * CT + 1 * NT + nn];
        float e12 = D1s[g * CT + 2 * NT + nn];
        float e20 = D2s[g * CT + 0 * NT + nn];
        float e21 = D2s[g * CT + 1 * NT + nn];
        float e22 = D2s[g * CT + 2 * NT + nn];
        float q0 = fmaf(m1[0], e10, fmaf(m1[1], e11, m1[2] * e12));
        float q1 = fmaf(m1[3], e10, fmaf(m1[4], e11, m1[5] * e12));
        float q2 = fmaf(m1[6], e10, fmaf(m1[7], e11, m1[8] * e12));
        float r0 = fmaf(m2[0], e20, fmaf(m2[1], e21, m2[2] * e22));
        float r1 = fmaf(m2[3], e20, fmaf(m2[4], e21, m2[5] * e22));
        float r2 = fmaf(m2[6], e20, fmaf(m2[7], e21, m2[8] * e22));
        float v0 = r1 * q2 - r2 * q1;
        float v1 = r2 * q0 - r0 * q2;
        float v2 = r0 * q1 - r1 * q0;

        size_t base = ((size_t)(b * F_ + g0 + g) * 3) * NDIM + n0 + nn;
        out[base]            = x[base]            + v0;
        out[base + NDIM]     = x[base + NDIM]     + v1;
        out[base + 2 * NDIM] = x[base + 2 * NDIM] + v2;
    }
}

extern "C" void kernel_launch(void* const* d_in, const int* in_sizes, int n_in,
                              void* d_out, int out_size)
{
    const float* x  = (const float*)d_in[0];
    const float* M1 = (const float*)d_in[1];
    const float* M2 = (const float*)d_in[2];
    const float* W1 = (const float*)d_in[3];
    const float* W2 = (const float*)d_in[4];
    float* out = (float*)d_out;

    cvt_x_kernel<<<1184, 256>>>(x);
    cvt_w_kernel<<<64, 256>>>(W1, W2);

    cudaFuncSetAttribute(lnlb_mma_kernel, cudaFuncAttributeMaxDynamicSharedMemorySize, SMEM_TOTAL);
    dim3 grid(NDIM / NT, F_ / GT, B_);   // (128, 4, 8)
    lnlb_mma_kernel<<<grid, THREADS, SMEM_TOTAL>>>(x, M1, M2, out);
}

// round 7
// speedup vs baseline: 1.8725x; 1.8725x over previous
#include <cuda_runtime.h>
#include <cuda_fp16.h>
#include <cstdint>

// LNLieBracketChannelMix via single-term fp16 mma.sync (fp32 accumulate).
// out[b,g,k,n] = x[b,g,k,n] + cross(M2@d2, M1@d1)[k],  d_i = W_i @ x[b] over f.
// R7: drop bf16 hi/lo split (3 MMAs) -> pure fp16 (1 MMA). 11-bit mantissa,
//     predicted rel_err ~2e-4 (<1e-3). Register-pipelined LDG->cvt->STS staging.

#define B_    8
#define F_    256
#define NDIM  4096
#define COLS  12288
#define GT    64
#define NT    32
#define CT    96
#define KC    32
#define NCH   8
#define THREADS 256

#define A_STRIDE 80                 // 32 fp16 = 64B + 16B pad
#define B_STRIDE 208                // 96 fp16 = 192B + 16B pad
#define A_PART   (GT * A_STRIDE)    // 5120 (one W tile)
#define B_OFF    (2 * A_PART)       // 10240
#define B_PART   (KC * B_STRIDE)    // 6656
#define STAGE    (B_OFF + B_PART)   // 16896
#define SMEM_TOTAL 49152            // epilogue D1/D2 (2*64*96*4) > 2*STAGE (33792)

static __device__ __forceinline__ uint32_t s2u(const void* p) {
    uint32_t a;
    asm("{ .reg .u64 t; cvta.to.shared.u64 t, %1; cvt.u32.u64 %0, t; }" : "=r"(a) : "l"(p));
    return a;
}
static __device__ __forceinline__ void lm4(uint32_t* r, uint32_t a) {
    asm volatile("ldmatrix.sync.aligned.m8n8.x4.shared.b16 {%0,%1,%2,%3}, [%4];"
        : "=r"(r[0]), "=r"(r[1]), "=r"(r[2]), "=r"(r[3]) : "r"(a));
}
static __device__ __forceinline__ void lm4t(uint32_t* r, uint32_t a) {
    asm volatile("ldmatrix.sync.aligned.m8n8.x4.trans.shared.b16 {%0,%1,%2,%3}, [%4];"
        : "=r"(r[0]), "=r"(r[1]), "=r"(r[2]), "=r"(r[3]) : "r"(a));
}
static __device__ __forceinline__ void mma(float* d, const uint32_t* a, uint32_t b0, uint32_t b1) {
    asm volatile(
        "mma.sync.aligned.m16n8k16.row.col.f32.f16.f16.f32 "
        "{%0,%1,%2,%3}, {%4,%5,%6,%7}, {%8,%9}, {%0,%1,%2,%3};"
        : "+f"(d[0]), "+f"(d[1]), "+f"(d[2]), "+f"(d[3])
        : "r"(a[0]), "r"(a[1]), "r"(a[2]), "r"(a[3]), "r"(b0), "r"(b1));
}
static __device__ __forceinline__ uint2 cvt4h(float4 v) {
    __half2 a = __floats2half2_rn(v.x, v.y);
    __half2 b = __floats2half2_rn(v.z, v.w);
    uint2 r;
    r.x = *reinterpret_cast<uint32_t*>(&a);
    r.y = *reinterpret_cast<uint32_t*>(&b);
    return r;
}

__global__ __launch_bounds__(THREADS, 2)
void lnlb_f16_kernel(const float* __restrict__ x,
                     const float* __restrict__ M1,
                     const float* __restrict__ M2,
                     const float* __restrict__ W1,
                     const float* __restrict__ W2,
                     float* __restrict__ out)
{
    extern __shared__ char smem[];
    const uint32_t sb = s2u(smem);

    const int tid = threadIdx.x;
    const int warp = tid >> 5, lane = tid & 31;
    const int n0 = blockIdx.x * NT;
    const int g0 = blockIdx.y * GT;
    const int b  = blockIdx.z;
    const float* xb = x + (size_t)b * F_ * COLS;

    const int mat = warp >> 2;           // 0 -> W1/D1, 1 -> W2/D2
    const int q   = warp & 3;
    const int wg  = (q >> 1) * 32;       // warp g offset within 64
    const int wc  = (q & 1) * 48;        // warp col offset within 96

    float acc[2][6][4];
    #pragma unroll
    for (int m = 0; m < 2; m++)
        #pragma unroll
        for (int t = 0; t < 6; t++)
            #pragma unroll
            for (int j = 0; j < 4; j++) acc[m][t][j] = 0.f;

    const int lrow = lane & 15;
    const uint32_t lhA = (lane & 16) ? 16u : 0u;
    const uint32_t lhB = (lane & 16) ? 8u  : 0u;
    uint32_t aoff[2], boff[3];
    #pragma unroll
    for (int m = 0; m < 2; m++) aoff[m] = (uint32_t)((wg + 16 * m + lrow) * A_STRIDE) + lhA;
    #pragma unroll
    for (int t = 0; t < 3; t++) boff[t] = (uint32_t)(lrow * B_STRIDE + (wc + t * 16 + lhB) * 2);
    const uint32_t aBase = (uint32_t)(mat * A_PART);

    // register-pipelined staging: LDG chunk into regs, later cvt+STS
    float4 ra[4], rb[3];
    auto ldchunk = [&](int c) {
        const int f0 = c * KC;
        #pragma unroll
        for (int j = 0; j < 4; j++) {          // A: 2 W tiles x 64 g x 8 f-quads
            int i = tid + j * THREADS;
            int t = i >> 9, r = i & 511, g = r >> 3, fq = r & 7;
            ra[j] = *(const float4*)((t ? W2 : W1) + (g0 + g) * F_ + f0 + fq * 4);
        }
        #pragma unroll
        for (int j = 0; j < 3; j++) {          // B: 32 f x 24 col-quads
            int i = tid + j * THREADS;
            int f = i / 24, cq = i % 24;
            rb[j] = *(const float4*)(xb + (size_t)(f0 + f) * COLS + (cq >> 3) * NDIM + n0 + (cq & 7) * 4);
        }
    };
    auto stchunk = [&](char* buf) {
        #pragma unroll
        for (int j = 0; j < 4; j++) {
            int i = tid + j * THREADS;
            int t = i >> 9, r = i & 511, g = r >> 3, fq = r & 7;
            *(uint2*)(buf + t * A_PART + g * A_STRIDE + fq * 8) = cvt4h(ra[j]);
        }
        #pragma unroll
        for (int j = 0; j < 3; j++) {
            int i = tid + j * THREADS;
            int f = i / 24, cq = i % 24;
            *(uint2*)(buf + B_OFF + f * B_STRIDE + cq * 8) = cvt4h(rb[j]);
        }
    };

    ldchunk(0);
    stchunk(smem);
    __syncthreads();

    for (int c = 0; c < NCH; ++c) {
        if (c + 1 < NCH) ldchunk(c + 1);          // LDGs in flight over MMA block

        const uint32_t bu = sb + (uint32_t)((c & 1) * STAGE);
        #pragma unroll
        for (int ks2 = 0; ks2 < 2; ++ks2) {
            const uint32_t ksA = ks2 * 32;
            const uint32_t ksB = ks2 * 16 * B_STRIDE;

            uint32_t Af[2][4];
            #pragma unroll
            for (int m = 0; m < 2; m++) lm4(Af[m], bu + aBase + aoff[m] + ksA);
            uint32_t Bf[3][4];
            #pragma unroll
            for (int t = 0; t < 3; t++) lm4t(Bf[t], bu + B_OFF + boff[t] + ksB);

            #pragma unroll
            for (int m = 0; m < 2; m++)
                #pragma unroll
                for (int t = 0; t < 3; t++) {
                    mma(acc[m][2*t],   Af[m], Bf[t][0], Bf[t][1]);
                    mma(acc[m][2*t+1], Af[m], Bf[t][2], Bf[t][3]);
                }
        }

        if (c + 1 < NCH) stchunk(smem + ((c + 1) & 1) * STAGE);
        __syncthreads();
    }

    // dump accumulators to smem (reuse stage buffers)
    float* D1s = (float*)smem;
    float* D2s = D1s + GT * CT;
    {
        float* Ds = mat ? D2s : D1s;
        const int dr = wg + (lane >> 2);
        const int dc = wc + (lane & 3) * 2;
        #pragma unroll
        for (int m = 0; m < 2; m++)
            #pragma unroll
            for (int t = 0; t < 6; t++) {
                int r0 = dr + 16 * m, cc = dc + t * 8;
                Ds[r0 * CT + cc]         = acc[m][t][0];
                Ds[r0 * CT + cc + 1]     = acc[m][t][1];
                Ds[(r0 + 8) * CT + cc]   = acc[m][t][2];
                Ds[(r0 + 8) * CT + cc+1] = acc[m][t][3];
            }
    }
    __syncthreads();

    // epilogue: rotate by M1/M2, cross, add x
    float m1[9], m2[9];
    #pragma unroll
    for (int i = 0; i < 9; i++) { m1[i] = M1[i]; m2[i] = M2[i]; }

    #pragma unroll
    for (int p = tid; p < GT * NT; p += THREADS) {
        int g = p >> 5, nn = p & 31;
        float e10 = D1s[g * CT + 0 * NT + nn];
        float e11 = D1s[g * CT + 1 * NT + nn];
        float e12 = D1s[g * CT + 2 * NT + nn];
        float e20 = D2s[g * CT + 0 * NT + nn];
        float e21 = D2s[g * CT + 1 * NT + nn];
        float e22 = D2s[g * CT + 2 * NT + nn];
        float q0 = fmaf(m1[0], e10, fmaf(m1[1], e11, m1[2] * e12));
        float q1 = fmaf(m1[3], e10, fmaf(m1[4], e11, m1[5] * e12));
        float q2 = fmaf(m1[6], e10, fmaf(m1[7], e11, m1[8] * e12));
        float r0 = fmaf(m2[0], e20, fmaf(m2[1], e21, m2[2] * e22));
        float r1 = fmaf(m2[3], e20, fmaf(m2[4], e21, m2[5] * e22));
        float r2 = fmaf(m2[6], e20, fmaf(m2[7], e21, m2[8] * e22));
        float v0 = r1 * q2 - r2 * q1;   // cross(M2 d2, M1 d1)
        float v1 = r2 * q0 - r0 * q2;
        float v2 = r0 * q1 - r1 * q0;

        size_t base = ((size_t)(b * F_ + g0 + g) * 3) * NDIM + n0 + nn;
        out[base]            = x[base]            + v0;
        out[base + NDIM]     = x[base + NDIM]     + v1;
        out[base + 2 * NDIM] = x[base + 2 * NDIM] + v2;
    }
}

extern "C" void kernel_launch(void* const* d_in, const int* in_sizes, int n_in,
                              void* d_out, int out_size)
{
    const float* x  = (const float*)d_in[0];
    const float* M1 = (const float*)d_in[1];
    const float* M2 = (const float*)d_in[2];
    const float* W1 = (const float*)d_in[3];
    const float* W2 = (const float*)d_in[4];
    float* out = (float*)d_out;

    cudaFuncSetAttribute(lnlb_f16_kernel, cudaFuncAttributeMaxDynamicSharedMemorySize, SMEM_TOTAL);
    dim3 grid(NDIM / NT, F_ / GT, B_);   // (128, 4, 8)
    lnlb_f16_kernel<<<grid, THREADS, SMEM_TOTAL>>>(x, M1, M2, W1, W2, out);
}